// round 17
// baseline (speedup 1.0000x reference)
#include <cuda_runtime.h>
#include <cuda_fp16.h>
#include <cstdint>
#include <math.h>

#define BB  2
#define LL  2048
#define DD  1024
#define HH  16
#define DHD 64
#define FFD 4096
#define MTOT (BB*LL)          // 4096 rows

// ---------------- scratch (static device globals; no allocation) -------------
__device__ float g_h [(size_t)MTOT*DD];    // pre-LN2 tensor (o@wo+bo+x)
__device__ float g_psum[BB*1024];
__device__ float g_psq [BB*1024];
__device__ float g_mu  [BB];
__device__ float g_rstd[BB];

// fp16 buffers (all single-precision fp16 activations)
__device__ __half g_a [(size_t)MTOT*DD];     // LN output
__device__ __half g_f [(size_t)MTOT*FFD];    // FFN hidden
__device__ __half g_q [(size_t)MTOT*DD];
__device__ __half g_k [(size_t)MTOT*DD];
__device__ __half g_v [(size_t)MTOT*DD];
__device__ __half g_o [(size_t)MTOT*DD];     // attention output
// fp16 weights (single-pass): wq@0, wk@1M, wv@2M, wo@3M, w1@4M(4M), w2@8M(4M)
#define WOFF_Q  ((size_t)0)
#define WOFF_K  ((size_t)1024*1024)
#define WOFF_V  ((size_t)2*1024*1024)
#define WOFF_O  ((size_t)3*1024*1024)
#define WOFF_1  ((size_t)4*1024*1024)
#define WOFF_2  ((size_t)8*1024*1024)
__device__ __half g_wh[(size_t)12*1024*1024];

// ======================= PTX helpers (baseline ISA, no 'a' features) =========
__device__ __forceinline__ uint32_t smem_u32(const void* p) {
    uint32_t a;
    asm("{ .reg .u64 t; cvta.to.shared.u64 t, %1; cvt.u32.u64 %0, t; }" : "=r"(a) : "l"(p));
    return a;
}
#define SWZ128(o) ((o) ^ (((o) >> 3) & 0x70))

#define CP_ASYNC16(dst, src) \
    asm volatile("cp.async.cg.shared.global [%0], [%1], 16;" :: "r"(dst), "l"(src))
#define CP_COMMIT() asm volatile("cp.async.commit_group;" ::: "memory")
#define CP_WAIT(n)  asm volatile("cp.async.wait_group %0;" :: "n"(n) : "memory")

__device__ __forceinline__ void ldsm_x4(uint32_t* r, uint32_t addr) {
    asm volatile("ldmatrix.sync.aligned.m8n8.x4.shared.b16 {%0,%1,%2,%3}, [%4];"
        : "=r"(r[0]), "=r"(r[1]), "=r"(r[2]), "=r"(r[3]) : "r"(addr));
}
__device__ __forceinline__ void ldsm_x4_t(uint32_t* r, uint32_t addr) {
    asm volatile("ldmatrix.sync.aligned.m8n8.x4.trans.shared.b16 {%0,%1,%2,%3}, [%4];"
        : "=r"(r[0]), "=r"(r[1]), "=r"(r[2]), "=r"(r[3]) : "r"(addr));
}
__device__ __forceinline__ void mma16816(float* c, const uint32_t* a, const uint32_t* b) {
    asm volatile(
        "mma.sync.aligned.m16n8k16.row.col.f32.f16.f16.f32 "
        "{%0,%1,%2,%3}, {%4,%5,%6,%7}, {%8,%9}, {%0,%1,%2,%3};"
        : "+f"(c[0]), "+f"(c[1]), "+f"(c[2]), "+f"(c[3])
        : "r"(a[0]), "r"(a[1]), "r"(a[2]), "r"(a[3]), "r"(b[0]), "r"(b[1]));
}
// pack two fp32 -> half2 bits (lo = p0, hi = p1)
__device__ __forceinline__ uint32_t pack_hf2(float p0, float p1) {
    __half2 h = __floats2half2_rn(p0, p1);
    return *(uint32_t*)&h;
}

// ---------------- LayerNorm over (L,D) jointly per batch ---------------------
__global__ void ln_partial(const float* __restrict__ x) {
    int b = blockIdx.y, blk = blockIdx.x;
    const float4* xb = (const float4*)x + (size_t)b*(LL*DD/4) + (size_t)blk*512;
    float s = 0.f, sq = 0.f;
    for (int i = threadIdx.x; i < 512; i += 256) {
        float4 v = xb[i];
        s  += v.x + v.y + v.z + v.w;
        sq += v.x*v.x + v.y*v.y + v.z*v.z + v.w*v.w;
    }
    __shared__ float ss[256], ssq[256];
    ss[threadIdx.x] = s; ssq[threadIdx.x] = sq;
    __syncthreads();
    for (int st = 128; st > 0; st >>= 1) {
        if (threadIdx.x < st) { ss[threadIdx.x] += ss[threadIdx.x+st]; ssq[threadIdx.x] += ssq[threadIdx.x+st]; }
        __syncthreads();
    }
    if (threadIdx.x == 0) { g_psum[b*1024+blk] = ss[0]; g_psq[b*1024+blk] = ssq[0]; }
}

__global__ void ln_finalize() {
    int b = blockIdx.x, tid = threadIdx.x;
    float s = 0.f, sq = 0.f;
    for (int i = tid; i < 1024; i += 256) { s += g_psum[b*1024+i]; sq += g_psq[b*1024+i]; }
    __shared__ float ss[256], ssq[256];
    ss[tid] = s; ssq[tid] = sq;
    __syncthreads();
    for (int st = 128; st > 0; st >>= 1) {
        if (tid < st) { ss[tid] += ss[tid+st]; ssq[tid] += ssq[tid+st]; }
        __syncthreads();
    }
    if (tid == 0) {
        float n   = (float)LL * (float)DD;
        float mu  = ss[0] / n;
        float var = ssq[0] / n - mu*mu;
        g_mu[b]   = mu;
        g_rstd[b] = rsqrtf(var + 1e-5f);
    }
}

// normalize -> single fp16
__global__ void ln_apply_f16(const float* __restrict__ in, __half* __restrict__ out) {
    int i = blockIdx.x*256 + threadIdx.x;           // float4 index
    int b = (i >= (LL*DD/4)) ? 1 : 0;
    float mu = g_mu[b], r = g_rstd[b];
    float4 v = ((const float4*)in)[i];
    uint2 p;
    p.x = pack_hf2((v.x-mu)*r, (v.y-mu)*r);
    p.y = pack_hf2((v.z-mu)*r, (v.w-mu)*r);
    ((uint2*)out)[i] = p;
}

// fused weight cast: all 6 weight matrices -> fp16 in one launch
// layout: [wq 256K][wk 256K][wv 256K][wo 256K][w1 1M][w2 1M]  (float4 units)
__global__ void cast_all_weights(
    const float* __restrict__ wq, const float* __restrict__ wk,
    const float* __restrict__ wv, const float* __restrict__ wo,
    const float* __restrict__ w1, const float* __restrict__ w2,
    __half* __restrict__ dst)
{
    int i = blockIdx.x*256 + threadIdx.x;   // float4 index, total 3M
    const float* src;
    size_t off;
    if      (i <  262144) { src = wq; off = 0; }
    else if (i <  524288) { src = wk; off = 262144; }
    else if (i <  786432) { src = wv; off = 524288; }
    else if (i < 1048576) { src = wo; off = 786432; }
    else if (i < 2097152) { src = w1; off = 1048576; }
    else                  { src = w2; off = 2097152; }
    float4 v = ((const float4*)src)[i - (int)off];
    uint2 p;
    p.x = pack_hf2(v.x, v.y);
    p.y = pack_hf2(v.z, v.w);
    ((uint2*)dst)[i] = p;
}

// =============== mma.sync GEMM: C[m,n] = sum_k A[m,k]*W[n,k] (+bias,resid,relu)
// CTA tile 128x128, K-chunk 64 fp16, 2-stage cp.async double buffer, 3 CTA/SM.
// Single-pass fp16 A and W.
#define TILEB 16384                 // one 128x64 fp16 tile (128B rows)
#define STAGE_BYTES (2*TILEB)       // A, B
#define MMG_SMEM (2*STAGE_BYTES + 1024)

__device__ __forceinline__ void issue_chunk(
    uint32_t sslot,
    const __half* a0, const __half* b0,
    int K, int k0, int tid)
{
    #pragma unroll
    for (int it = 0; it < 4; it++) {
        int idx = it*256 + tid;
        int row = idx >> 3, s = idx & 7;
        uint32_t off = SWZ128((uint32_t)(row*128 + s*16));
        size_t go = (size_t)row*K + k0 + s*8;
        CP_ASYNC16(sslot + off,         a0 + go);
        CP_ASYNC16(sslot + TILEB + off, b0 + go);
    }
}

__global__ __launch_bounds__(256, 3) void mm_gemm(
    const __half* __restrict__ A, const __half* __restrict__ Bw,
    const float* __restrict__ bias, const float* __restrict__ resid,
    float* __restrict__ C, __half* __restrict__ Chi,
    int M, int N, int K, int relu)
{
    extern __shared__ char smraw[];
    char* smb = (char*)(((uintptr_t)smraw + 1023) & ~(uintptr_t)1023);
    uint32_t sbase = smem_u32(smb);

    const int tid  = threadIdx.x;
    const int warp = tid >> 5, lane = tid & 31;
    const int m0 = blockIdx.y * 128, n0 = blockIdx.x * 128;
    const int wm = (warp >> 1) * 32;
    const int wn = (warp & 1) * 64;

    const __half* tA = A  + (size_t)m0 * K;
    const __half* tB = Bw + (size_t)n0 * K;

    float acc[2][8][4];
    #pragma unroll
    for (int i = 0; i < 2; i++)
        #pragma unroll
        for (int j = 0; j < 8; j++)
            #pragma unroll
            for (int q = 0; q < 4; q++) acc[i][j][q] = 0.f;

    const int nch = K >> 6;
    issue_chunk(sbase, tA, tB, K, 0, tid);
    CP_COMMIT();

    const int arow  = (lane & 7) + ((lane >> 3) & 1) * 8;
    const int akoff = (lane >> 4) * 16;
    const int brow  = (lane & 7) + (lane >> 4) * 8;
    const int bkoff = ((lane >> 3) & 1) * 16;

    for (int c = 0; c < nch; c++) {
        __syncthreads();            // all warps done reading the buffer we refill
        if (c + 1 < nch) {
            issue_chunk(sbase + ((c+1)&1)*STAGE_BYTES, tA, tB, K, (c+1)*64, tid);
            CP_COMMIT();
            CP_WAIT(1);
        } else {
            CP_WAIT(0);
        }
        __syncthreads();

        uint32_t sl = sbase + (c & 1)*STAGE_BYTES;
        #pragma unroll
        for (int ks = 0; ks < 4; ks++) {
            uint32_t ah[2][4];
            #pragma unroll
            for (int mf = 0; mf < 2; mf++) {
                uint32_t off = SWZ128((uint32_t)((wm + mf*16 + arow)*128 + ks*32 + akoff));
                ldsm_x4(ah[mf], sl + off);
            }
            #pragma unroll
            for (int g = 0; g < 4; g++) {
                uint32_t bh[4];
                uint32_t off = SWZ128((uint32_t)((wn + g*16 + brow)*128 + ks*32 + bkoff));
                ldsm_x4(bh, sl + TILEB + off);
                #pragma unroll
                for (int mf = 0; mf < 2; mf++) {
                    mma16816(acc[mf][2*g],   ah[mf], bh);
                    mma16816(acc[mf][2*g+1], ah[mf], bh + 2);
                }
            }
        }
    }

    // epilogue
    const int rbase = m0 + wm + (lane >> 2);
    const int cbase = n0 + wn + (lane & 3) * 2;
    #pragma unroll
    for (int nf = 0; nf < 8; nf++) {
        const int col = cbase + nf*8;
        float2 bv = *(const float2*)(bias + col);
        #pragma unroll
        for (int mf = 0; mf < 2; mf++) {
            int r0 = rbase + mf*16;
            #pragma unroll
            for (int half_ = 0; half_ < 2; half_++) {
                int rr = r0 + half_*8;
                float vx = acc[mf][nf][half_*2+0] + bv.x;
                float vy = acc[mf][nf][half_*2+1] + bv.y;
                if (resid) {
                    float2 rv = *(const float2*)(resid + (size_t)rr*N + col);
                    vx += rv.x; vy += rv.y;
                }
                if (relu) { vx = fmaxf(vx, 0.f); vy = fmaxf(vy, 0.f); }
                if (Chi) {
                    *(uint32_t*)(Chi + (size_t)rr*N + col) = pack_hf2(vx, vy);
                } else {
                    float2 v2 = make_float2(vx, vy);
                    *(float2*)(C + (size_t)rr*N + col) = v2;
                }
            }
        }
    }
}

// ======= tensor-core flash attention: O = softmax(Q K^T * 0.25) V ============
// CTA: 128 q-rows of one (b,h). 8 warps x 16 rows. Key tiles of 64.
// Single-pass fp16 Q,K,V; fp32 softmax; P fp16.
// smem: Q 16KB + 2 stages x (k,v) 16KB = 48KB.
#define ATT_Q_BYTES 16384
#define ATT_KV_STAGE 16384
#define ATT_SMEM (ATT_Q_BYTES + 2*ATT_KV_STAGE)

__device__ __forceinline__ void attn_issue_kv(
    uint32_t kvs,
    const __half* k, const __half* v,
    size_t gbase, int tid)
{
    #pragma unroll
    for (int t = 0; t < 2; t++) {
        int idx = t*256 + tid;
        int row = idx >> 3, seg = idx & 7;
        uint32_t off = SWZ128((uint32_t)(row*128 + seg*16));
        size_t go = gbase + (size_t)row*DD + seg*8;
        CP_ASYNC16(kvs + off,         k + go);
        CP_ASYNC16(kvs + 8192 + off,  v + go);
    }
}

__global__ __launch_bounds__(256) void attn_tc(
    const __half* __restrict__ q,
    const __half* __restrict__ k,
    const __half* __restrict__ v,
    __half* __restrict__ o)
{
    extern __shared__ char smraw[];
    uint32_t sb = smem_u32(smraw);
    const int tid = threadIdx.x, warp = tid >> 5, lane = tid & 31;
    const int qt = blockIdx.x;
    const int b = blockIdx.y >> 4, h = blockIdx.y & 15;
    const int wm = warp * 16;

    const size_t qbase  = ((size_t)(b*LL + qt*128))*DD + (size_t)h*DHD;
    const size_t kvbase = ((size_t)(b*LL))*DD + (size_t)h*DHD;

    // prologue: Q + KV tile 0 -> one group
    #pragma unroll
    for (int t = 0; t < 4; t++) {
        int idx = t*256 + tid;
        int row = idx >> 3, seg = idx & 7;
        uint32_t off = SWZ128((uint32_t)(row*128 + seg*16));
        size_t go = qbase + (size_t)row*DD + seg*8;
        CP_ASYNC16(sb + off, q + go);
    }
    attn_issue_kv(sb + ATT_Q_BYTES, k, v, kvbase, tid);
    CP_COMMIT();

    float sO[8][4];
    #pragma unroll
    for (int j = 0; j < 8; j++)
        #pragma unroll
        for (int qq = 0; qq < 4; qq++) sO[j][qq] = 0.f;
    float mrow[2] = {-1e30f, -1e30f};
    float lrow[2] = {0.f, 0.f};

    const int arow  = (lane & 7) + ((lane >> 3) & 1) * 8;
    const int akoff = (lane >> 4) * 16;
    const int brow  = (lane & 7) + (lane >> 4) * 8;
    const int bkoff = ((lane >> 3) & 1) * 16;
    const int vgrp  = lane >> 3, vr = lane & 7;   // trans-ldsm addressing

    const int NT = LL / 64;   // 32 key tiles
    for (int kt = 0; kt < NT; kt++) {
        __syncthreads();
        if (kt + 1 < NT) {
            attn_issue_kv(sb + ATT_Q_BYTES + ((kt+1)&1)*ATT_KV_STAGE,
                          k, v, kvbase + (size_t)(kt+1)*64*DD, tid);
            CP_COMMIT();
            CP_WAIT(1);
        } else {
            CP_WAIT(0);
        }
        __syncthreads();

        uint32_t kvs = sb + ATT_Q_BYTES + (kt&1)*ATT_KV_STAGE;

        // ---- S = Q K^T ----
        float sS[8][4];
        #pragma unroll
        for (int j = 0; j < 8; j++)
            #pragma unroll
            for (int qq = 0; qq < 4; qq++) sS[j][qq] = 0.f;

        #pragma unroll
        for (int ks = 0; ks < 4; ks++) {
            uint32_t aq[4];
            uint32_t offa = SWZ128((uint32_t)((wm + arow)*128 + ks*32 + akoff));
            ldsm_x4(aq, sb + offa);
            #pragma unroll
            for (int g = 0; g < 4; g++) {
                uint32_t bh_[4];
                uint32_t offb = SWZ128((uint32_t)((g*16 + brow)*128 + ks*32 + bkoff));
                ldsm_x4(bh_, kvs + offb);
                mma16816(sS[2*g],   aq, bh_);
                mma16816(sS[2*g+1], aq, bh_ + 2);
            }
        }

        // scale (faithful source bug: 1/sqrt(H) = 0.25)
        #pragma unroll
        for (int j = 0; j < 8; j++)
            #pragma unroll
            for (int qq = 0; qq < 4; qq++) sS[j][qq] *= 0.25f;

        // ---- online softmax (rows: rr=0 -> lane>>2, rr=1 -> +8) ----
        #pragma unroll
        for (int rr = 0; rr < 2; rr++) {
            float tm = -1e30f;
            #pragma unroll
            for (int j = 0; j < 8; j++) {
                tm = fmaxf(tm, sS[j][rr*2+0]);
                tm = fmaxf(tm, sS[j][rr*2+1]);
            }
            tm = fmaxf(tm, __shfl_xor_sync(0xffffffffu, tm, 1));
            tm = fmaxf(tm, __shfl_xor_sync(0xffffffffu, tm, 2));
            float mnew = fmaxf(mrow[rr], tm);
            float corr = __expf(mrow[rr] - mnew);
            mrow[rr] = mnew;
            float psum = 0.f;
            #pragma unroll
            for (int j = 0; j < 8; j++) {
                float p0 = __expf(sS[j][rr*2+0] - mnew);
                float p1 = __expf(sS[j][rr*2+1] - mnew);
                sS[j][rr*2+0] = p0; sS[j][rr*2+1] = p1;
                psum += p0 + p1;
            }
            psum += __shfl_xor_sync(0xffffffffu, psum, 1);
            psum += __shfl_xor_sync(0xffffffffu, psum, 2);
            lrow[rr] = lrow[rr]*corr + psum;
            #pragma unroll
            for (int j = 0; j < 8; j++) {
                sO[j][rr*2+0] *= corr;
                sO[j][rr*2+1] *= corr;
            }
        }

        // ---- pack P (A-fragments for PV, fp16) ----
        uint32_t pa[4][4];
        #pragma unroll
        for (int kk = 0; kk < 4; kk++) {
            pa[kk][0] = pack_hf2(sS[2*kk][0],   sS[2*kk][1]);
            pa[kk][1] = pack_hf2(sS[2*kk][2],   sS[2*kk][3]);
            pa[kk][2] = pack_hf2(sS[2*kk+1][0], sS[2*kk+1][1]);
            pa[kk][3] = pack_hf2(sS[2*kk+1][2], sS[2*kk+1][3]);
        }

        // ---- O += P V ----
        #pragma unroll
        for (int ks = 0; ks < 4; ks++) {
            #pragma unroll
            for (int g = 0; g < 4; g++) {
                uint32_t bv_[4];
                int row = ks*16 + (vgrp & 1)*8 + vr;
                int colb = (g*16 + (vgrp >> 1)*8) * 2;
                uint32_t offv = SWZ128((uint32_t)(row*128 + colb));
                ldsm_x4_t(bv_, kvs + 8192 + offv);
                mma16816(sO[2*g],   pa[ks], bv_);
                mma16816(sO[2*g+1], pa[ks], bv_ + 2);
            }
        }
    }

    // ---- epilogue: normalize + fp16 store ----
    #pragma unroll
    for (int rr = 0; rr < 2; rr++) {
        float inv = 1.0f / lrow[rr];
        int row = qt*128 + wm + rr*8 + (lane >> 2);
        size_t ob = ((size_t)(b*LL + row))*DD + (size_t)h*DHD + (lane & 3)*2;
        #pragma unroll
        for (int j = 0; j < 8; j++) {
            float v0 = sO[j][rr*2+0] * inv;
            float v1 = sO[j][rr*2+1] * inv;
            *(uint32_t*)(o + ob + j*8) = pack_hf2(v0, v1);
        }
    }
}

// ---------------- launcher ---------------------------------------------------
extern "C" void kernel_launch(void* const* d_in, const int* in_sizes, int n_in,
                              void* d_out, int out_size) {
    const float* x  = (const float*)d_in[0];
    const float* wq = (const float*)d_in[1];
    const float* bq = (const float*)d_in[2];
    const float* wk = (const float*)d_in[3];
    const float* bk = (const float*)d_in[4];
    const float* wv = (const float*)d_in[5];
    const float* bv = (const float*)d_in[6];
    const float* wo = (const float*)d_in[7];
    const float* bo = (const float*)d_in[8];
    const float* w1 = (const float*)d_in[9];
    const float* b1 = (const float*)d_in[10];
    const float* w2 = (const float*)d_in[11];
    const float* b2 = (const float*)d_in[12];
    float* out = (float*)d_out;

    cudaFuncSetAttribute((const void*)mm_gemm,
                         cudaFuncAttributeMaxDynamicSharedMemorySize, MMG_SMEM);
    cudaFuncSetAttribute((const void*)attn_tc,
                         cudaFuncAttributeMaxDynamicSharedMemorySize, ATT_SMEM);

    void *ph_, *pa, *pf, *pwh, *pq, *pk, *pv, *po;
    cudaGetSymbolAddress(&ph_, g_h);
    cudaGetSymbolAddress(&pa,  g_a);
    cudaGetSymbolAddress(&pf,  g_f);
    cudaGetSymbolAddress(&pwh, g_wh);
    cudaGetSymbolAddress(&pq,  g_q);
    cudaGetSymbolAddress(&pk,  g_k);
    cudaGetSymbolAddress(&pv,  g_v);
    cudaGetSymbolAddress(&po,  g_o);
    float* h = (float*)ph_;
    __half* a  = (__half*)pa;
    __half* f  = (__half*)pf;
    __half* wh = (__half*)pwh;
    __half* q  = (__half*)pq;
    __half* k  = (__half*)pk;
    __half* v  = (__half*)pv;
    __half* o  = (__half*)po;

    dim3 gRed(1024, BB);
    dim3 gProj(DD/128,  MTOT/128);   // (8, 32)
    dim3 gFF1 (FFD/128, MTOT/128);   // (32, 32)
    dim3 gAtt (LL/128, BB*HH);       // (16, 32)

    // fused weight cast (single launch, 3M float4)
    cast_all_weights<<<12288, 256>>>(wq, wk, wv, wo, w1, w2, wh);

    // LN1 -> fp16 activations
    ln_partial<<<gRed, 256>>>(x);
    ln_finalize<<<BB, 256>>>();
    ln_apply_f16<<<4096, 256>>>(x, a);
    // QKV projections (single-pass fp16)
    mm_gemm<<<gProj, 256, MMG_SMEM>>>(a, wh + WOFF_Q, bq, nullptr, nullptr, q, MTOT, DD, DD, 0);
    mm_gemm<<<gProj, 256, MMG_SMEM>>>(a, wh + WOFF_K, bk, nullptr, nullptr, k, MTOT, DD, DD, 0);
    mm_gemm<<<gProj, 256, MMG_SMEM>>>(a, wh + WOFF_V, bv, nullptr, nullptr, v, MTOT, DD, DD, 0);
    // tensor-core flash attention -> fp16 o
    attn_tc<<<gAtt, 256, ATT_SMEM>>>(q, k, v, o);
    // output projection + residual(x) -> h (fp32)
    mm_gemm<<<gProj, 256, MMG_SMEM>>>(o, wh + WOFF_O, bo, x, h, nullptr, MTOT, DD, DD, 0);
    // LN2 -> fp16
    ln_partial<<<gRed, 256>>>(h);
    ln_finalize<<<BB, 256>>>();
    ln_apply_f16<<<4096, 256>>>(h, a);
    // FFN1 (relu) -> fp16 hidden
    mm_gemm<<<gFF1, 256, MMG_SMEM>>>(a, wh + WOFF_1, b1, nullptr, nullptr, f, MTOT, FFD, DD, 1);
    // FFN2 + residual(x) -> out (fp32)
    mm_gemm<<<gProj, 256, MMG_SMEM>>>(f, wh + WOFF_2, b2, x, out, nullptr, MTOT, DD, FFD, 0);
}